// round 12
// baseline (speedup 1.0000x reference)
#include <cuda_runtime.h>
#include <cuda_fp16.h>

#define BB   256
#define NN   1152
#define OO   10
#define JJ   160              // floats per (b,n): j = o*16+k
#define WW   80
#define EPSF 1e-7f
#define NPART 16
#define NPERW 18              // n per warp = 1152/(NPART*4); 6 steps of 3
#define NSTEP 6

typedef unsigned long long ull;

// ---- scratch (static device globals; no allocation) ----
__device__ __half2 g_uh[(size_t)BB * NN * WW];     // 94.5 MB, [b][n][w]
__device__ float   g_part[36 * BB * JJ];           // 5.9 MB uhat partials
__device__ float   g_s0[BB * JJ];
__device__ float   g_sA[BB * JJ];
__device__ float   g_sB[BB * JJ];

// ---- packed f32x2 helpers ----
__device__ __forceinline__ ull fma2(ull a, ull b, ull c) {
    ull d; asm("fma.rn.f32x2 %0, %1, %2, %3;" : "=l"(d) : "l"(a), "l"(b), "l"(c));
    return d;
}
__device__ __forceinline__ ull add2(ull a, ull b) {
    ull d; asm("add.rn.f32x2 %0, %1, %2;" : "=l"(d) : "l"(a), "l"(b));
    return d;
}
__device__ __forceinline__ ull pack2(float lo, float hi) {
    ull d; asm("mov.b64 %0, {%1, %2};" : "=l"(d) : "f"(lo), "f"(hi));
    return d;
}
__device__ __forceinline__ float2 unpack2(ull v) {
    float lo, hi; asm("mov.b64 {%0, %1}, %2;" : "=f"(lo), "=f"(hi) : "l"(v));
    return make_float2(lo, hi);
}
// f32 group-sum via s32 REDUX (sm_80+).  Scale 2^18: e<=~150, 10 lanes
// -> itot < 4e8 < 2^31.  Quantization ~2e-5 rel, far under the fp16 floor.
#define REDUX_SCALE 262144.f
#define REDUX_INV   (1.f / 262144.f)
__device__ __forceinline__ float redux_add_f32i(float v, unsigned mask) {
    int iv = __float2int_rn(v * REDUX_SCALE);
    int r; asm("redux.sync.add.s32 %0, %1, %2;" : "=r"(r) : "r"(iv), "r"(mask));
    return (float)r * REDUX_INV;
}

// ---------------------------------------------------------------------------
__global__ void k_zero() {
    int i = blockIdx.x * blockDim.x + threadIdx.x;
    if (i < BB * JJ) { g_s0[i] = 0.f; g_sA[i] = 0.f; g_sB[i] = 0.f; }
}

// ---------------------------------------------------------------------------
// u_hat via packed f32x2 FMA, 32 n per block (round-9 proven form).
__global__ void __launch_bounds__(160) k_uhat(const float* __restrict__ x,
                                              const float* __restrict__ w) {
    const int j  = threadIdx.x;
    const int n0 = blockIdx.x * 32;
    const int b0 = blockIdx.y * 32;

    __shared__ __align__(16) float x_sm[32 * 64];   // [bb][i*8+n]
    __shared__ float acc_sm[32][JJ];

    for (int idx = j; idx < 32 * JJ; idx += 160) ((float*)acc_sm)[idx] = 0.f;

    const int wb = (j >> 4) * 128 + (j & 15);
    __half* gh = (__half*)g_uh;
    const ull z2 = pack2(0.f, 0.f);

    for (int c = 0; c < 4; c++) {
        const int n0c = n0 + c * 8;
        __syncthreads();
        for (int idx = j; idx < 32 * 64; idx += 160) {
            int bb = idx >> 6, q = idx & 63;
            int n = q >> 3, i = q & 7;
            x_sm[bb * 64 + i * 8 + n] =
                x[(size_t)(b0 + bb) * (NN * 8) + (n0c + n) * 8 + i];
        }
        ull Wp[4][8];
        #pragma unroll
        for (int p = 0; p < 4; p++)
            #pragma unroll
            for (int i = 0; i < 8; i++) {
                float a = w[(size_t)(n0c + 2 * p)     * 1280 + wb + i * 16];
                float b = w[(size_t)(n0c + 2 * p + 1) * 1280 + wb + i * 16];
                Wp[p][i] = pack2(a, b);
            }
        __syncthreads();

        for (int bb = 0; bb < 32; bb++) {
            ull s2 = z2;
            __half* outp = &gh[((size_t)(b0 + bb) * NN + n0c) * JJ + j];
            const ull* xrow = (const ull*)&x_sm[bb * 64];
            #pragma unroll
            for (int p = 0; p < 4; p++) {
                ull acc = z2;
                #pragma unroll
                for (int i = 0; i < 8; i++)
                    acc = fma2(Wp[p][i], xrow[i * 4 + p], acc);
                s2 = add2(s2, acc);
                float2 u = unpack2(acc);
                outp[(2 * p)     * JJ] = __float2half(u.x);
                outp[(2 * p + 1) * JJ] = __float2half(u.y);
            }
            float2 sf = unpack2(s2);
            acc_sm[bb][j] += sf.x + sf.y;
        }
    }
    __syncthreads();
    for (int bb = 0; bb < 32; bb++)
        g_part[((size_t)blockIdx.x * BB + (b0 + bb)) * JJ + j] = acc_sm[bb][j];
}

// ---------------------------------------------------------------------------
__global__ void k_red0() {
    const int b = blockIdx.x, j = threadIdx.x;
    const int nb0 = blockIdx.y * 9;
    float s = 0.f;
    #pragma unroll 3
    for (int nb = nb0; nb < nb0 + 9; nb++)
        s += g_part[((size_t)nb * BB + b) * JJ + j];
    atomicAdd(&g_s0[b * JJ + j], s);
}

// ---------------------------------------------------------------------------
__global__ void k_squash(const float* __restrict__ sbuf, float scale,
                         const float* __restrict__ bias, float* __restrict__ dst) {
    const int b = blockIdx.x, j = threadIdx.x;
    float s = scale * sbuf[b * JJ + j] + bias[j];
    float d = s * s;
    #pragma unroll
    for (int msk = 1; msk < 16; msk <<= 1)
        d += __shfl_xor_sync(0xffffffffu, d, msk, 16);
    dst[b * JJ + j] = s * (d / ((1.f + d) * sqrtf(d + EPSF)));
}

__device__ __forceinline__ float squash1(float s) {
    float d = s * s;
    #pragma unroll
    for (int msk = 1; msk < 16; msk <<= 1)
        d += __shfl_xor_sync(0xffffffffu, d, msk, 16);
    return s * (d / ((1.f + d) * sqrtf(d + EPSF)));
}

// ---------------------------------------------------------------------------
// Routing iteration: 30-lane / 3-n layout + s32-REDUX softmax.  b1-free.
// grid (256 b, NPART), block 128 (4 warps).  Lane l<30: g = l/10 (n triplet
// member), o = l%10.  Lane-local 16-k dot; tot = REDUX over 10-lane group.
template <int ITER>
__global__ void __launch_bounds__(128, 8) k_route(const float* __restrict__ s0in,
                                                  const float* __restrict__ sAin,
                                                  const float* __restrict__ bias,
                                                  float* __restrict__ sout) {
    const int b   = blockIdx.x;
    const int tid = threadIdx.x;
    const int wp  = tid >> 5, l = tid & 31;
    const bool act = (l < 30);
    const int g = act ? (l / 10) : 0;
    const int o = act ? (l % 10) : 0;
    const unsigned rmask = 0x3FFu << (10 * g);

    __shared__ __align__(16) float vsum_sm[JJ];
    {
        float v = squash1(0.1f * s0in[b * JJ + tid] + bias[tid]);
        if (ITER == 2) v += squash1(sAin[b * JJ + tid] + bias[tid]);
        vsum_sm[tid] = v;
        if (tid < 32) {
            int j2 = 128 + tid;
            float v2 = squash1(0.1f * s0in[b * JJ + j2] + bias[j2]);
            if (ITER == 2) v2 += squash1(sAin[b * JJ + j2] + bias[j2]);
            vsum_sm[j2] = v2;
        }
    }
    __syncthreads();

    float vreg[16];
    {
        const float4* vp = (const float4*)&vsum_sm[o * 16];
        #pragma unroll
        for (int q = 0; q < 4; q++) {
            float4 t = vp[q];
            vreg[4 * q] = t.x; vreg[4 * q + 1] = t.y;
            vreg[4 * q + 2] = t.z; vreg[4 * q + 3] = t.w;
        }
    }

    float sacc[16];
    #pragma unroll
    for (int k = 0; k < 16; k++) sacc[k] = 0.f;

    const int nbeg = (blockIdx.y * 4 + wp) * NPERW;
    const char* ub = (const char*)g_uh + ((size_t)b * NN + nbeg) * 320
                   + g * 320 + o * 32;

    // software pipeline: preload step 0
    float4 A0 = make_float4(0.f, 0.f, 0.f, 0.f), B0 = A0, A1, B1;
    if (act) {
        A0 = *(const float4*)ub;
        B0 = *(const float4*)(ub + 16);
    }

    #pragma unroll
    for (int s = 0; s < NSTEP; s++) {
        if (s + 1 < NSTEP) {
            const char* np = ub + (s + 1) * 960;
            A1 = act ? *(const float4*)np        : make_float4(0.f, 0.f, 0.f, 0.f);
            B1 = act ? *(const float4*)(np + 16) : make_float4(0.f, 0.f, 0.f, 0.f);
        }
        const __half2* h2a = (const __half2*)&A0;
        const __half2* h2b = (const __half2*)&B0;
        float acc = 0.f;
        #pragma unroll
        for (int i = 0; i < 4; i++) {
            float2 t = __half22float2(h2a[i]);
            acc = fmaf(t.x, vreg[2 * i], fmaf(t.y, vreg[2 * i + 1], acc));
        }
        #pragma unroll
        for (int i = 0; i < 4; i++) {
            float2 t = __half22float2(h2b[i]);
            acc = fmaf(t.x, vreg[8 + 2 * i], fmaf(t.y, vreg[8 + 2 * i + 1], acc));
        }
        float c = 0.f;
        if (act) {
            float e = __expf(acc);
            float tot = redux_add_f32i(e, rmask);    // Σ_o within 10-lane group
            c = __fdividef(e, tot);
        }
        #pragma unroll
        for (int i = 0; i < 4; i++) {
            float2 t = __half22float2(h2a[i]);
            sacc[2 * i]     = fmaf(c, t.x, sacc[2 * i]);
            sacc[2 * i + 1] = fmaf(c, t.y, sacc[2 * i + 1]);
        }
        #pragma unroll
        for (int i = 0; i < 4; i++) {
            float2 t = __half22float2(h2b[i]);
            sacc[8 + 2 * i]     = fmaf(c, t.x, sacc[8 + 2 * i]);
            sacc[8 + 2 * i + 1] = fmaf(c, t.y, sacc[8 + 2 * i + 1]);
        }
        A0 = A1; B0 = B1;
    }

    // merge: [4 warps][3 triplet members][160]
    __shared__ __align__(16) float ssm[4][3][JJ];
    if (act) {
        float4* sp = (float4*)&ssm[wp][g][o * 16];
        #pragma unroll
        for (int q = 0; q < 4; q++)
            sp[q] = make_float4(sacc[4 * q], sacc[4 * q + 1],
                                sacc[4 * q + 2], sacc[4 * q + 3]);
    }
    __syncthreads();

    for (int jj = tid; jj < JJ; jj += 128) {
        float s = 0.f;
        #pragma unroll
        for (int w4 = 0; w4 < 4; w4++)
            s += ssm[w4][0][jj] + ssm[w4][1][jj] + ssm[w4][2][jj];
        atomicAdd(&sout[b * JJ + jj], s);
    }
}

// ---------------------------------------------------------------------------
extern "C" void kernel_launch(void* const* d_in, const int* in_sizes, int n_in,
                              void* d_out, int out_size) {
    const float* x    = (const float*)d_in[0];
    const float* w    = (const float*)d_in[1];
    const float* bias = (const float*)d_in[2];
    float* out = (float*)d_out;

    float* s0; cudaGetSymbolAddress((void**)&s0, g_s0);
    float* sA; cudaGetSymbolAddress((void**)&sA, g_sA);
    float* sB; cudaGetSymbolAddress((void**)&sB, g_sB);

    k_zero<<<40, 1024>>>();
    k_uhat<<<dim3(36, 8), 160>>>(x, w);
    k_red0<<<dim3(256, 4), 160>>>();
    k_route<1><<<dim3(256, NPART), 128>>>(s0, nullptr, bias, sA);  // iter 1
    k_route<2><<<dim3(256, NPART), 128>>>(s0, sA, bias, sB);       // iter 2
    k_squash<<<256, 160>>>(sB, 1.0f, bias, out);                   // final
}

// round 13
// speedup vs baseline: 1.0161x; 1.0161x over previous
#include <cuda_runtime.h>
#include <cuda_fp16.h>

#define BB   256
#define NN   1152
#define OO   10
#define JJ   160              // floats per (b,n): j = o*16+k
#define WW   80
#define EPSF 1e-7f
#define NPART 18
#define NPERW 16              // n per warp: 1152/(NPART*4)

typedef unsigned long long ull;

// ---- scratch (static device globals; no allocation) ----
__device__ __half2 g_uh[(size_t)BB * NN * WW];     // 94.5 MB, [b][n][w]
__device__ float   g_part[36 * BB * JJ];           // 5.9 MB uhat partials
__device__ float   g_s0[BB * JJ];
__device__ float   g_sA[BB * JJ];
__device__ float   g_sB[BB * JJ];

// ---- packed f32x2 helpers ----
__device__ __forceinline__ ull fma2(ull a, ull b, ull c) {
    ull d; asm("fma.rn.f32x2 %0, %1, %2, %3;" : "=l"(d) : "l"(a), "l"(b), "l"(c));
    return d;
}
__device__ __forceinline__ ull add2(ull a, ull b) {
    ull d; asm("add.rn.f32x2 %0, %1, %2;" : "=l"(d) : "l"(a), "l"(b));
    return d;
}
__device__ __forceinline__ ull pack2(float lo, float hi) {
    ull d; asm("mov.b64 %0, {%1, %2};" : "=l"(d) : "f"(lo), "f"(hi));
    return d;
}
__device__ __forceinline__ float2 unpack2(ull v) {
    float lo, hi; asm("mov.b64 {%0, %1}, %2;" : "=f"(lo), "=f"(hi) : "l"(v));
    return make_float2(lo, hi);
}

// ---------------------------------------------------------------------------
__global__ void k_zero() {
    int i = blockIdx.x * blockDim.x + threadIdx.x;
    if (i < BB * JJ) { g_s0[i] = 0.f; g_sA[i] = 0.f; g_sB[i] = 0.f; }
}

// ---------------------------------------------------------------------------
// u_hat via packed f32x2 FMA, 32 n per block; stores staged through smem so
// gmem traffic is STG.128 coalesced (was 1024 scattered STG.16 per thread).
// grid (36, 8), block 160 (thread = j).
__global__ void __launch_bounds__(160) k_uhat(const float* __restrict__ x,
                                              const float* __restrict__ w) {
    const int j  = threadIdx.x;
    const int n0 = blockIdx.x * 32;
    const int b0 = blockIdx.y * 32;

    __shared__ __align__(16) float x_sm[32 * 64];      // [bb][i*8+n]  8 KB
    __shared__ float acc_sm[32][JJ];                   // s0 partials  20 KB
    __shared__ __align__(16) __half st_sm[8 * 8 * JJ]; // [bb8][n][j]  20 KB

    for (int idx = j; idx < 32 * JJ; idx += 160) ((float*)acc_sm)[idx] = 0.f;

    const int wb = (j >> 4) * 128 + (j & 15);          // o*128 + k
    __half* gh = (__half*)g_uh;
    const ull z2 = pack2(0.f, 0.f);

    for (int c = 0; c < 4; c++) {
        const int n0c = n0 + c * 8;
        __syncthreads();
        for (int idx = j; idx < 32 * 64; idx += 160) {
            int bb = idx >> 6, q = idx & 63;           // q = n*8+i
            int n = q >> 3, i = q & 7;
            x_sm[bb * 64 + i * 8 + n] =
                x[(size_t)(b0 + bb) * (NN * 8) + (n0c + n) * 8 + i];
        }
        ull Wp[4][8];
        #pragma unroll
        for (int p = 0; p < 4; p++)
            #pragma unroll
            for (int i = 0; i < 8; i++) {
                float a = w[(size_t)(n0c + 2 * p)     * 1280 + wb + i * 16];
                float b = w[(size_t)(n0c + 2 * p + 1) * 1280 + wb + i * 16];
                Wp[p][i] = pack2(a, b);
            }
        __syncthreads();

        for (int bg = 0; bg < 4; bg++) {               // 4 groups of 8 bb
            #pragma unroll
            for (int bb8 = 0; bb8 < 8; bb8++) {
                const int bb = bg * 8 + bb8;
                ull s2 = z2;
                const ull* xrow = (const ull*)&x_sm[bb * 64];
                #pragma unroll
                for (int p = 0; p < 4; p++) {
                    ull acc = z2;
                    #pragma unroll
                    for (int i = 0; i < 8; i++)
                        acc = fma2(Wp[p][i], xrow[i * 4 + p], acc);
                    s2 = add2(s2, acc);
                    float2 u = unpack2(acc);
                    st_sm[bb8 * (8 * JJ) + (2 * p)     * JJ + j] = __float2half(u.x);
                    st_sm[bb8 * (8 * JJ) + (2 * p + 1) * JJ + j] = __float2half(u.y);
                }
                float2 sf = unpack2(s2);
                acc_sm[bb][j] += sf.x + sf.y;
            }
            __syncthreads();
            // flush 8 bb x 8 n x 160 j halves = 1280 int4, coalesced
            const int4* src = (const int4*)st_sm;
            for (int idx = j; idx < 1280; idx += 160) {
                int bb8 = idx / 160, rem = idx - bb8 * 160;
                int n = rem / 20, col = rem - n * 20;
                int4 v = src[idx];
                *(int4*)&gh[((size_t)(b0 + bg * 8 + bb8) * NN + n0c + n) * JJ + col * 8] = v;
            }
            __syncthreads();
        }
    }
    __syncthreads();
    for (int bb = 0; bb < 32; bb++)
        g_part[((size_t)blockIdx.x * BB + (b0 + bb)) * JJ + j] = acc_sm[bb][j];
}

// ---------------------------------------------------------------------------
__global__ void k_red0() {
    const int b = blockIdx.x, j = threadIdx.x;
    const int nb0 = blockIdx.y * 9;
    float s = 0.f;
    #pragma unroll 3
    for (int nb = nb0; nb < nb0 + 9; nb++)
        s += g_part[((size_t)nb * BB + b) * JJ + j];
    atomicAdd(&g_s0[b * JJ + j], s);
}

// ---------------------------------------------------------------------------
__global__ void k_squash(const float* __restrict__ sbuf, float scale,
                         const float* __restrict__ bias, float* __restrict__ dst) {
    const int b = blockIdx.x, j = threadIdx.x;
    float s = scale * sbuf[b * JJ + j] + bias[j];
    float d = s * s;
    #pragma unroll
    for (int msk = 1; msk < 16; msk <<= 1)
        d += __shfl_xor_sync(0xffffffffu, d, msk, 16);
    dst[b * JJ + j] = s * (d / ((1.f + d) * sqrtf(d + EPSF)));
}

__device__ __forceinline__ float squash1(float s) {
    float d = s * s;
    #pragma unroll
    for (int msk = 1; msk < 16; msk <<= 1)
        d += __shfl_xor_sync(0xffffffffu, d, msk, 16);
    return s * (d / ((1.f + d) * sqrtf(d + EPSF)));
}

// ---------------------------------------------------------------------------
// Routing iteration (round-9 proven form): 2-n-per-warp-step, b1-free,
// 2-pair groups, <=64 regs.  grid (256 b, NPART), block 128.
// Lane l<20: parity = l&1 (n vs n+1), o = l>>1.
template <int ITER>
__global__ void __launch_bounds__(128, 8) k_route(const float* __restrict__ s0in,
                                                  const float* __restrict__ sAin,
                                                  const float* __restrict__ bias,
                                                  float* __restrict__ sout) {
    const int b   = blockIdx.x;
    const int tid = threadIdx.x;
    const int wp  = tid >> 5, l = tid & 31;
    const unsigned FULL = 0xffffffffu;
    const bool act = (l < 20);

    __shared__ __align__(16) float vsum_sm[JJ];
    {
        float v = squash1(0.1f * s0in[b * JJ + tid] + bias[tid]);
        if (ITER == 2) v += squash1(sAin[b * JJ + tid] + bias[tid]);
        vsum_sm[tid] = v;
        if (tid < 32) {
            int j2 = 128 + tid;
            float v2 = squash1(0.1f * s0in[b * JJ + j2] + bias[j2]);
            if (ITER == 2) v2 += squash1(sAin[b * JJ + j2] + bias[j2]);
            vsum_sm[j2] = v2;
        }
    }
    __syncthreads();

    float vreg[16];
    {
        const int o = l >> 1;
        const float4* vp = (const float4*)&vsum_sm[(act ? o : 0) * 16];
        #pragma unroll
        for (int q = 0; q < 4; q++) {
            float4 t = vp[q];
            vreg[4 * q] = t.x; vreg[4 * q + 1] = t.y;
            vreg[4 * q + 2] = t.z; vreg[4 * q + 3] = t.w;
        }
    }

    float sacc[16];
    #pragma unroll
    for (int k = 0; k < 16; k++) sacc[k] = 0.f;

    const int nbeg = (blockIdx.y * 4 + wp) * NPERW;
    const char* ub = (const char*)g_uh + ((size_t)b * NN + nbeg) * 320
                   + (l & 1) * 320 + (l >> 1) * 32;

    for (int g = 0; g < 4; g++) {                    // 4 groups of 2 pairs
        float4 A[2], Bq[2];
        #pragma unroll
        for (int p = 0; p < 2; p++) {
            const char* ap = ub + (g * 2 + p) * 640;
            A[p]  = act ? *(const float4*)ap        : make_float4(0.f, 0.f, 0.f, 0.f);
            Bq[p] = act ? *(const float4*)(ap + 16) : make_float4(0.f, 0.f, 0.f, 0.f);
        }
        #pragma unroll
        for (int p = 0; p < 2; p++) {
            const __half2* h2a = (const __half2*)&A[p];
            const __half2* h2b = (const __half2*)&Bq[p];
            float acc = 0.f;
            #pragma unroll
            for (int i = 0; i < 4; i++) {
                float2 t = __half22float2(h2a[i]);
                acc = fmaf(t.x, vreg[2 * i], fmaf(t.y, vreg[2 * i + 1], acc));
            }
            #pragma unroll
            for (int i = 0; i < 4; i++) {
                float2 t = __half22float2(h2b[i]);
                acc = fmaf(t.x, vreg[8 + 2 * i], fmaf(t.y, vreg[8 + 2 * i + 1], acc));
            }
            float e = act ? __expf(acc) : 0.f;
            float tot = e;                           // Σ over same-parity lanes
            tot += __shfl_xor_sync(FULL, tot, 2);
            tot += __shfl_xor_sync(FULL, tot, 4);
            tot += __shfl_xor_sync(FULL, tot, 8);
            tot += __shfl_xor_sync(FULL, tot, 16);
            float c = __fdividef(e, tot);
            #pragma unroll
            for (int i = 0; i < 4; i++) {
                float2 t = __half22float2(h2a[i]);
                sacc[2 * i]     = fmaf(c, t.x, sacc[2 * i]);
                sacc[2 * i + 1] = fmaf(c, t.y, sacc[2 * i + 1]);
            }
            #pragma unroll
            for (int i = 0; i < 4; i++) {
                float2 t = __half22float2(h2b[i]);
                sacc[8 + 2 * i]     = fmaf(c, t.x, sacc[8 + 2 * i]);
                sacc[8 + 2 * i + 1] = fmaf(c, t.y, sacc[8 + 2 * i + 1]);
            }
        }
    }

    __shared__ __align__(16) float ssm[4][2][JJ];
    if (act) {
        float4* sp = (float4*)&ssm[wp][l & 1][(l >> 1) * 16];
        #pragma unroll
        for (int q = 0; q < 4; q++)
            sp[q] = make_float4(sacc[4 * q], sacc[4 * q + 1],
                                sacc[4 * q + 2], sacc[4 * q + 3]);
    }
    __syncthreads();

    for (int jj = tid; jj < JJ; jj += 128) {
        float s = 0.f;
        #pragma unroll
        for (int w4 = 0; w4 < 4; w4++)
            s += ssm[w4][0][jj] + ssm[w4][1][jj];
        atomicAdd(&sout[b * JJ + jj], s);
    }
}

// ---------------------------------------------------------------------------
extern "C" void kernel_launch(void* const* d_in, const int* in_sizes, int n_in,
                              void* d_out, int out_size) {
    const float* x    = (const float*)d_in[0];
    const float* w    = (const float*)d_in[1];
    const float* bias = (const float*)d_in[2];
    float* out = (float*)d_out;

    float* s0; cudaGetSymbolAddress((void**)&s0, g_s0);
    float* sA; cudaGetSymbolAddress((void**)&sA, g_sA);
    float* sB; cudaGetSymbolAddress((void**)&sB, g_sB);

    k_zero<<<40, 1024>>>();
    k_uhat<<<dim3(36, 8), 160>>>(x, w);
    k_red0<<<dim3(256, 4), 160>>>();
    k_route<1><<<dim3(256, NPART), 128>>>(s0, nullptr, bias, sA);  // iter 1
    k_route<2><<<dim3(256, NPART), 128>>>(s0, sA, bias, sB);       // iter 2
    k_squash<<<256, 160>>>(sB, 1.0f, bias, out);                   // final
}

// round 16
// speedup vs baseline: 1.0702x; 1.0532x over previous
#include <cuda_runtime.h>
#include <cuda_fp16.h>

#define BB   256
#define NN   1152
#define OO   10
#define JJ   160              // floats per (b,n): j = o*16+k
#define WW   80
#define EPSF 1e-7f
#define NPART 18
#define NPERW 16              // n per warp: 1152/(NPART*4)

typedef unsigned long long ull;

// ---- scratch (static device globals; no allocation) ----
__device__ __half2 g_uh[(size_t)BB * NN * WW];     // 94.5 MB, [b][n][w]
__device__ float   g_part[144 * BB * JJ];          // 23.6 MB uhat partials
__device__ float   g_s0[BB * JJ];
__device__ float   g_sA[BB * JJ];
__device__ float   g_sB[BB * JJ];

// ---- packed f32x2 helpers ----
__device__ __forceinline__ ull fma2(ull a, ull b, ull c) {
    ull d; asm("fma.rn.f32x2 %0, %1, %2, %3;" : "=l"(d) : "l"(a), "l"(b), "l"(c));
    return d;
}
__device__ __forceinline__ ull add2(ull a, ull b) {
    ull d; asm("add.rn.f32x2 %0, %1, %2;" : "=l"(d) : "l"(a), "l"(b));
    return d;
}
__device__ __forceinline__ ull pack2(float lo, float hi) {
    ull d; asm("mov.b64 %0, {%1, %2};" : "=l"(d) : "f"(lo), "f"(hi));
    return d;
}
__device__ __forceinline__ float2 unpack2(ull v) {
    float lo, hi; asm("mov.b64 {%0, %1}, %2;" : "=f"(lo), "=f"(hi) : "l"(v));
    return make_float2(lo, hi);
}

// ---------------------------------------------------------------------------
__global__ void k_zero() {
    int i = blockIdx.x * blockDim.x + threadIdx.x;
    if (i < BB * JJ) { g_s0[i] = 0.f; g_sA[i] = 0.f; g_sB[i] = 0.f; }
}

// ---------------------------------------------------------------------------
// u_hat via packed f32x2 FMA over n-pairs (round-7 proven form: (144,8) grid,
// 8 n per block, direct fp16 stores, high block count for latency hiding).
__global__ void __launch_bounds__(160) k_uhat(const float* __restrict__ x,
                                              const float* __restrict__ w) {
    const int j  = threadIdx.x;
    const int n0 = blockIdx.x * 8;
    const int b0 = blockIdx.y * 32;

    __shared__ __align__(16) float x_sm[32 * 64];   // [bb][i*8+n]
    for (int idx = j; idx < 32 * 64; idx += 160) {
        int bb = idx >> 6, q = idx & 63;            // q = n*8+i in source order
        int n = q >> 3, i = q & 7;
        x_sm[bb * 64 + i * 8 + n] = x[(size_t)(b0 + bb) * (NN * 8) + (n0 + n) * 8 + i];
    }

    ull Wp[4][8];                                    // (W[n], W[n+1]) pairs
    {
        const int wb = (j >> 4) * 128 + (j & 15);    // o*128 + k
        #pragma unroll
        for (int p = 0; p < 4; p++)
            #pragma unroll
            for (int i = 0; i < 8; i++) {
                float a = w[(size_t)(n0 + 2 * p)     * 1280 + wb + i * 16];
                float b = w[(size_t)(n0 + 2 * p + 1) * 1280 + wb + i * 16];
                Wp[p][i] = pack2(a, b);
            }
    }
    __syncthreads();

    __half* gh = (__half*)g_uh;
    const ull z2 = pack2(0.f, 0.f);
    for (int bb = 0; bb < 32; bb++) {
        ull s2 = z2;
        __half* outp = &gh[((size_t)(b0 + bb) * NN + n0) * JJ + j];
        const ull* xrow = (const ull*)&x_sm[bb * 64];
        #pragma unroll
        for (int p = 0; p < 4; p++) {
            ull acc = z2;
            #pragma unroll
            for (int i = 0; i < 8; i++)
                acc = fma2(Wp[p][i], xrow[i * 4 + p], acc);   // broadcast LDS.64
            s2 = add2(s2, acc);
            float2 u = unpack2(acc);
            outp[(2 * p)     * JJ] = __float2half(u.x);
            outp[(2 * p + 1) * JJ] = __float2half(u.y);
        }
        float2 sf = unpack2(s2);
        g_part[((size_t)blockIdx.x * BB + (b0 + bb)) * JJ + j] = sf.x + sf.y;
    }
}

// ---------------------------------------------------------------------------
__global__ void k_red0() {
    const int b = blockIdx.x, j = threadIdx.x;
    const int nb0 = blockIdx.y * 18;
    float s = 0.f;
    #pragma unroll 6
    for (int nb = nb0; nb < nb0 + 18; nb++)
        s += g_part[((size_t)nb * BB + b) * JJ + j];
    atomicAdd(&g_s0[b * JJ + j], s);
}

// ---------------------------------------------------------------------------
__global__ void k_squash(const float* __restrict__ sbuf, float scale,
                         const float* __restrict__ bias, float* __restrict__ dst) {
    const int b = blockIdx.x, j = threadIdx.x;
    float s = scale * sbuf[b * JJ + j] + bias[j];
    float d = s * s;
    #pragma unroll
    for (int msk = 1; msk < 16; msk <<= 1)
        d += __shfl_xor_sync(0xffffffffu, d, msk, 16);
    dst[b * JJ + j] = s * (d / ((1.f + d) * sqrtf(d + EPSF)));
}

__device__ __forceinline__ float squash1(float s) {
    float d = s * s;
    #pragma unroll
    for (int msk = 1; msk < 16; msk <<= 1)
        d += __shfl_xor_sync(0xffffffffu, d, msk, 16);
    return s * (d / ((1.f + d) * sqrtf(d + EPSF)));
}

// ---------------------------------------------------------------------------
// Routing iteration (round-9 proven form): 2-n-per-warp-step, b1-free,
// 2-pair groups, <=64 regs.  grid (256 b, NPART), block 128.
// Lane l<20: parity = l&1 (n vs n+1), o = l>>1.
template <int ITER>
__global__ void __launch_bounds__(128, 8) k_route(const float* __restrict__ s0in,
                                                  const float* __restrict__ sAin,
                                                  const float* __restrict__ bias,
                                                  float* __restrict__ sout) {
    const int b   = blockIdx.x;
    const int tid = threadIdx.x;
    const int wp  = tid >> 5, l = tid & 31;
    const unsigned FULL = 0xffffffffu;
    const bool act = (l < 20);

    __shared__ __align__(16) float vsum_sm[JJ];
    {
        float v = squash1(0.1f * s0in[b * JJ + tid] + bias[tid]);
        if (ITER == 2) v += squash1(sAin[b * JJ + tid] + bias[tid]);
        vsum_sm[tid] = v;
        if (tid < 32) {
            int j2 = 128 + tid;
            float v2 = squash1(0.1f * s0in[b * JJ + j2] + bias[j2]);
            if (ITER == 2) v2 += squash1(sAin[b * JJ + j2] + bias[j2]);
            vsum_sm[j2] = v2;
        }
    }
    __syncthreads();

    float vreg[16];
    {
        const int o = l >> 1;
        const float4* vp = (const float4*)&vsum_sm[(act ? o : 0) * 16];
        #pragma unroll
        for (int q = 0; q < 4; q++) {
            float4 t = vp[q];
            vreg[4 * q] = t.x; vreg[4 * q + 1] = t.y;
            vreg[4 * q + 2] = t.z; vreg[4 * q + 3] = t.w;
        }
    }

    float sacc[16];
    #pragma unroll
    for (int k = 0; k < 16; k++) sacc[k] = 0.f;

    const int nbeg = (blockIdx.y * 4 + wp) * NPERW;
    const char* ub = (const char*)g_uh + ((size_t)b * NN + nbeg) * 320
                   + (l & 1) * 320 + (l >> 1) * 32;

    for (int g = 0; g < 4; g++) {                    // 4 groups of 2 pairs
        float4 A[2], Bq[2];
        #pragma unroll
        for (int p = 0; p < 2; p++) {
            const char* ap = ub + (g * 2 + p) * 640;
            A[p]  = act ? *(const float4*)ap        : make_float4(0.f, 0.f, 0.f, 0.f);
            Bq[p] = act ? *(const float4*)(ap + 16) : make_float4(0.f, 0.f, 0.f, 0.f);
        }
        #pragma unroll
        for (int p = 0; p < 2; p++) {
            const __half2* h2a = (const __half2*)&A[p];
            const __half2* h2b = (const __half2*)&Bq[p];
            float acc = 0.f;
            #pragma unroll
            for (int i = 0; i < 4; i++) {
                float2 t = __half22float2(h2a[i]);
                acc = fmaf(t.x, vreg[2 * i], fmaf(t.y, vreg[2 * i + 1], acc));
            }
            #pragma unroll
            for (int i = 0; i < 4; i++) {
                float2 t = __half22float2(h2b[i]);
                acc = fmaf(t.x, vreg[8 + 2 * i], fmaf(t.y, vreg[8 + 2 * i + 1], acc));
            }
            float e = act ? __expf(acc) : 0.f;
            float tot = e;                           // Σ over same-parity lanes
            tot += __shfl_xor_sync(FULL, tot, 2);
            tot += __shfl_xor_sync(FULL, tot, 4);
            tot += __shfl_xor_sync(FULL, tot, 8);
            tot += __shfl_xor_sync(FULL, tot, 16);
            float c = __fdividef(e, tot);
            #pragma unroll
            for (int i = 0; i < 4; i++) {
                float2 t = __half22float2(h2a[i]);
                sacc[2 * i]     = fmaf(c, t.x, sacc[2 * i]);
                sacc[2 * i + 1] = fmaf(c, t.y, sacc[2 * i + 1]);
            }
            #pragma unroll
            for (int i = 0; i < 4; i++) {
                float2 t = __half22float2(h2b[i]);
                sacc[8 + 2 * i]     = fmaf(c, t.x, sacc[8 + 2 * i]);
                sacc[8 + 2 * i + 1] = fmaf(c, t.y, sacc[8 + 2 * i + 1]);
            }
        }
    }

    __shared__ __align__(16) float ssm[4][2][JJ];
    if (act) {
        float4* sp = (float4*)&ssm[wp][l & 1][(l >> 1) * 16];
        #pragma unroll
        for (int q = 0; q < 4; q++)
            sp[q] = make_float4(sacc[4 * q], sacc[4 * q + 1],
                                sacc[4 * q + 2], sacc[4 * q + 3]);
    }
    __syncthreads();

    for (int jj = tid; jj < JJ; jj += 128) {
        float s = 0.f;
        #pragma unroll
        for (int w4 = 0; w4 < 4; w4++)
            s += ssm[w4][0][jj] + ssm[w4][1][jj];
        atomicAdd(&sout[b * JJ + jj], s);
    }
}

// ---------------------------------------------------------------------------
extern "C" void kernel_launch(void* const* d_in, const int* in_sizes, int n_in,
                              void* d_out, int out_size) {
    const float* x    = (const float*)d_in[0];
    const float* w    = (const float*)d_in[1];
    const float* bias = (const float*)d_in[2];
    float* out = (float*)d_out;

    float* s0; cudaGetSymbolAddress((void**)&s0, g_s0);
    float* sA; cudaGetSymbolAddress((void**)&sA, g_sA);
    float* sB; cudaGetSymbolAddress((void**)&sB, g_sB);

    k_zero<<<40, 1024>>>();
    k_uhat<<<dim3(144, 8), 160>>>(x, w);
    k_red0<<<dim3(256, 8), 160>>>();
    k_route<1><<<dim3(256, NPART), 128>>>(s0, nullptr, bias, sA);  // iter 1
    k_route<2><<<dim3(256, NPART), 128>>>(s0, sA, bias, sB);       // iter 2
    k_squash<<<256, 160>>>(sB, 1.0f, bias, out);                   // final
}